// round 4
// baseline (speedup 1.0000x reference)
#include <cuda_runtime.h>
#include <math.h>

#define N_NODES 256
#define E_EDGES 320
#define DE      640
#define HV      128
#define MV      128
#define DISD    8
#define ANGD    16
#define CAP     64
#define WATT_LD 416
#define WLNK_LD 264
#define NBLK    148
#define NTHR    256

// ---------------- scratch ----------------
__device__ int   g_U[DE], g_V[DE];
__device__ float g_norm[DE * 3];
__device__ float g_align[DE];
__device__ float g_a[DE * MV];
__device__ float g_b[DE * MV];
__device__ float g_att[DE * MV];
__device__ float g_attsum[4 * MV];
__device__ float g_wc[ANGD * MV];      // W_att[:,400:416] transposed [k][m]
__device__ int   g_adjU_cnt[N_NODES], g_adjV_cnt[N_NODES];
__device__ int   g_adjU[N_NODES * CAP], g_adjV[N_NODES * CAP];

// ---------------- grid barrier (sense-reversing, replay-safe) ----------------
__device__ unsigned g_bar_cnt = 0;
__device__ volatile unsigned g_bar_sense = 0;

__device__ __forceinline__ void grid_barrier() {
    __threadfence();            // release: all threads' prior writes visible
    __syncthreads();
    if (threadIdx.x == 0) {
        unsigned s = g_bar_sense;
        if (atomicAdd(&g_bar_cnt, 1u) == NBLK - 1) {
            g_bar_cnt = 0;
            __threadfence();
            g_bar_sense = s + 1;
        } else {
            while (g_bar_sense == s) { __nanosleep(32); }
        }
    }
    __syncthreads();
    __threadfence();            // acquire
}

__device__ __forceinline__ float dot4(float4 a, float4 b) {
    return a.x * b.x + a.y * b.y + a.z * b.z + a.w * b.w;
}

__global__ void __launch_bounds__(NTHR, 2)
k_fused(const float* __restrict__ hv, const float* __restrict__ he,
        const float* __restrict__ q,
        const float* __restrict__ vew1, const float* __restrict__ vew2,
        const float* __restrict__ W_dis, const float* __restrict__ b_dis,
        const float* __restrict__ W_ang, const float* __restrict__ b_ang,
        const float* __restrict__ W_att,
        const float* __restrict__ W_align, const float* __restrict__ b_align,
        const float* __restrict__ W_link, const float* __restrict__ b_link,
        float* __restrict__ out) {
    const int t = threadIdx.x;
    const int lane = t & 31;
    const int gw = blockIdx.x * 8 + (t >> 5);   // global warp id [0,1184)

    __shared__ __align__(16) float su[HV], sv[HV], sdis[DISD];
    __shared__ float spart[3][6][64];           // split-K partials (h=1..3)

    // ================= Phase A: decode + adjacency + align + misc =============
    for (int idx = blockIdx.x * NTHR + t; idx < N_NODES * E_EDGES; idx += NBLK * NTHR) {
        int e = idx % E_EDGES, n = idx / E_EDGES;
        if (vew1[idx] != 0.0f) { g_U[e] = n; g_V[e + E_EDGES] = n; }
        if (vew2[idx] != 0.0f) { g_V[e] = n; g_U[e + E_EDGES] = n; }
    }
    if (gw < 256) {                              // adjacency: one warp per node
        int n = gw;
        unsigned lml = (1u << lane) - 1u;
        int cu = 0, cv = 0;
        for (int e0 = 0; e0 < E_EDGES; e0 += 32) {
            int e = e0 + lane;
            float a = vew1[n * E_EDGES + e];
            float c = vew2[n * E_EDGES + e];
            unsigned m1 = __ballot_sync(0xFFFFFFFFu, a != 0.0f);
            unsigned m2 = __ballot_sync(0xFFFFFFFFu, c != 0.0f);
            if (a != 0.0f) g_adjU[n * CAP + cu + __popc(m1 & lml)] = e;
            if (c != 0.0f) g_adjV[n * CAP + cv + __popc(m2 & lml)] = e;
            cu += __popc(m1); cv += __popc(m2);
        }
        for (int e0 = 0; e0 < E_EDGES; e0 += 32) {
            int e = e0 + lane;
            float a = vew1[n * E_EDGES + e];
            float c = vew2[n * E_EDGES + e];
            unsigned m1 = __ballot_sync(0xFFFFFFFFu, c != 0.0f);
            unsigned m2 = __ballot_sync(0xFFFFFFFFu, a != 0.0f);
            if (c != 0.0f) g_adjU[n * CAP + cu + __popc(m1 & lml)] = e + E_EDGES;
            if (a != 0.0f) g_adjV[n * CAP + cv + __popc(m2 & lml)] = e + E_EDGES;
            cu += __popc(m1); cv += __popc(m2);
        }
        if (lane == 0) { g_adjU_cnt[n] = cu; g_adjV_cnt[n] = cv; }
    } else if (gw < 576) {                       // align logit: one warp per edge
        int e = gw - 256;
        float val = 0.0f;
        #pragma unroll
        for (int k = 0; k < 4; k++) {
            int c = lane + 32 * k;
            val += he[e * HV + c] * W_align[c];
        }
        #pragma unroll
        for (int s = 16; s > 0; s >>= 1) val += __shfl_down_sync(0xFFFFFFFFu, val, s);
        if (lane == 0) {
            float al = val + b_align[0];
            g_align[e] = al;
            g_align[e + E_EDGES] = al;
        }
    } else if (gw < 640) {                       // wc transpose (2048 entries)
        int j = (gw - 576) * 32 + lane;
        int k = j >> 7, m = j & 127;
        g_wc[j] = W_att[m * WATT_LD + 400 + k];
    } else if (gw < 656) {                       // zero attsum (512 entries)
        g_attsum[(gw - 640) * 32 + lane] = 0.0f;
    }

    grid_barrier();

    // ================= Phase B: fused GEMM + me epilogue ======================
    // block = (col-group, edge-group); 64 cols/block -> weight slice fits L1
    {
        const int cg = blockIdx.x & 1;
        const int eg = blockIdx.x >> 1;          // [0,74)
        const int ml = t & 63;
        const int m  = cg * 64 + ml;
        const int h  = t >> 6;                   // 4-way split-K
        const float4* wrow = (const float4*)(W_att + m * WATT_LD);
        const float4* lrow = (const float4*)(W_link + m * WLNK_LD);
        const float4* pu = (const float4*)su;
        const float4* pv = (const float4*)sv;
        const float4* pd = (const float4*)sdis;

        for (int e = eg; e < E_EDGES; e += 74) {
            int u = g_U[e], v = g_V[e];
            __syncthreads();                     // prev iter fully consumed
            if (t < 128) su[t] = hv[u * HV + t];
            else         sv[t - 128] = hv[v * HV + (t - 128)];
            if (t == 0) {
                float qx = q[v * 3 + 0] - q[u * 3 + 0];
                float qy = q[v * 3 + 1] - q[u * 3 + 1];
                float qz = q[v * 3 + 2] - q[u * 3 + 2];
                float dis = sqrtf(qx * qx + qy * qy + qz * qz) + 1e-6f;
                float inv = 1.0f / dis;
                g_norm[e * 3 + 0] = qx * inv;
                g_norm[e * 3 + 1] = qy * inv;
                g_norm[e * 3 + 2] = qz * inv;
                g_norm[(e + E_EDGES) * 3 + 0] = -qx * inv;
                g_norm[(e + E_EDGES) * 3 + 1] = -qy * inv;
                g_norm[(e + E_EDGES) * 3 + 2] = -qz * inv;
                float td = tanhf(dis);
                #pragma unroll
                for (int k = 0; k < DISD; k++)
                    sdis[k] = tanhf(td * W_dis[k] + b_dis[k]);
            }
            __syncthreads();

            float aaf = 0.f, aar = 0.f, bbf = 0.f, bbr = 0.f, mmf = 0.f, mmr = 0.f;
            int k0 = h * 8;
            #pragma unroll
            for (int kk = 0; kk < 8; kk++) {
                int k = k0 + kk;
                float4 wva = wrow[k];            // A: hv_v  cols [0,128)
                float4 wua = wrow[34 + k];       // A: hv_u  cols [136,264)
                float4 wvb = wrow[66 + k];       // b: hv_v  cols [264,392)
                float4 wum = lrow[k];            // link: hv_u
                float4 wvm = lrow[34 + k];       // link: hv_v
                float4 uu = pu[k], vv = pv[k];
                aaf += dot4(vv, wva) + dot4(uu, wua);
                aar += dot4(uu, wva) + dot4(vv, wua);   // reverse edge: swap u/v
                bbf += dot4(vv, wvb);
                bbr += dot4(uu, wvb);
                mmf += dot4(uu, wum) + dot4(vv, wvm);
                mmr += dot4(vv, wum) + dot4(uu, wvm);
            }
            if (h == 0) {                        // dis block (shared fwd/rev)
                #pragma unroll
                for (int kk = 0; kk < 2; kk++) {
                    float4 wda = wrow[32 + kk];  // A: dis cols [128,136)
                    float4 wdb = wrow[98 + kk];  // b: dis cols [392,400)
                    float4 wdm = lrow[32 + kk];  // link: dis
                    float4 dd = pd[kk];
                    float da = dot4(dd, wda), db = dot4(dd, wdb), dm = dot4(dd, wdm);
                    aaf += da; aar += da;
                    bbf += db; bbr += db;
                    mmf += dm; mmr += dm;
                }
            }

            if (h > 0) {
                spart[h - 1][0][ml] = aaf; spart[h - 1][1][ml] = aar;
                spart[h - 1][2][ml] = bbf; spart[h - 1][3][ml] = bbr;
                spart[h - 1][4][ml] = mmf; spart[h - 1][5][ml] = mmr;
            }
            __syncthreads();
            if (h == 0) {
                #pragma unroll
                for (int p = 0; p < 3; p++) {
                    aaf += spart[p][0][ml]; aar += spart[p][1][ml];
                    bbf += spart[p][2][ml]; bbr += spart[p][3][ml];
                    mmf += spart[p][4][ml]; mmr += spart[p][5][ml];
                }
                g_a[e * MV + m] = aaf;
                g_a[(e + E_EDGES) * MV + m] = aar;
                g_b[e * MV + m] = bbf;
                g_b[(e + E_EDGES) * MV + m] = bbr;
                float x = mmf + mmr + 2.0f * b_link[m];
                out[N_NODES * MV + e * MV + m] = (x >= 0.0f) ? x : 0.01f * x;
            }
        }
    }

    grid_barrier();

    // ================= Phase C: sparse attend (sync-free, per-warp) ===========
    {
        float wang = 0.f, bang = 0.f;
        if (lane < ANGD) { wang = W_ang[lane]; bang = b_ang[lane]; }
        for (int wt = gw; wt < DE * 4; wt += NBLK * 8) {
            int i = wt >> 2;
            int m = (wt & 3) * 32 + lane;
            float wc[ANGD];
            #pragma unroll
            for (int k = 0; k < ANGD; k++) wc[k] = g_wc[k * MV + m];
            float ai = g_a[i * MV + m];
            float nix = g_norm[i * 3 + 0], niy = g_norm[i * 3 + 1], niz = g_norm[i * 3 + 2];
            int u = g_U[i];
            int cnt = g_adjU_cnt[u];
            float amax = 0.0f;                   // relu floor
            for (int idx = 0; idx < cnt; idx++) {
                int j = g_adjU[u * CAP + idx];
                float ang = nix * g_norm[j * 3 + 0] + niy * g_norm[j * 3 + 1]
                          + niz * g_norm[j * 3 + 2];
                float sh = 0.0f;
                if (lane < ANGD) sh = tanhf(ang * wang + bang);
                float c = 0.0f;
                #pragma unroll
                for (int k = 0; k < ANGD; k++)
                    c += __shfl_sync(0xFFFFFFFFu, sh, k) * wc[k];
                amax = fmaxf(amax, ai + g_b[j * MV + m] + c);
            }
            g_att[i * MV + m] = amax;
            atomicAdd(&g_attsum[(i & 3) * MV + m], amax);
        }
    }

    grid_barrier();

    // ================= Phase D: softmax-gather + elu -> mv ====================
    if (gw < N_NODES * 4) {
        int n = gw >> 2;
        int m = (gw & 3) * 32 + lane;
        int cnt = g_adjV_cnt[n];
        float r;
        if (cnt == 0) {
            r = (g_attsum[m] + g_attsum[MV + m] + g_attsum[2 * MV + m]
                 + g_attsum[3 * MV + m]) * (1.0f / (float)DE);
        } else {
            float mx = -1e30f;
            for (int idx = 0; idx < cnt; idx++)
                mx = fmaxf(mx, g_align[g_adjV[n * CAP + idx]]);
            float den = 0.0f, acc = 0.0f;
            for (int idx = 0; idx < cnt; idx++) {
                int d = g_adjV[n * CAP + idx];
                float w = expf(g_align[d] - mx);
                den += w;
                acc += w * g_att[d * MV + m];
            }
            r = acc / den;
        }
        out[n * MV + m] = (r > 0.0f) ? r : expm1f(r);
    }
}

// ---------------- launch ----------------
extern "C" void kernel_launch(void* const* d_in, const int* in_sizes, int n_in,
                              void* d_out, int out_size) {
    const float* hv      = (const float*)d_in[0];
    const float* he      = (const float*)d_in[1];
    const float* q       = (const float*)d_in[3];
    const float* vew1    = (const float*)d_in[4];
    const float* vew2    = (const float*)d_in[5];
    const float* W_dis   = (const float*)d_in[8];
    const float* b_dis   = (const float*)d_in[9];
    const float* W_ang   = (const float*)d_in[10];
    const float* b_ang   = (const float*)d_in[11];
    const float* W_att   = (const float*)d_in[12];
    const float* W_align = (const float*)d_in[13];
    const float* b_align = (const float*)d_in[14];
    const float* W_link  = (const float*)d_in[15];
    const float* b_link  = (const float*)d_in[16];
    float* out = (float*)d_out;

    k_fused<<<NBLK, NTHR>>>(hv, he, q, vew1, vew2, W_dis, b_dis, W_ang, b_ang,
                            W_att, W_align, b_align, W_link, b_link, out);
}

// round 5
// speedup vs baseline: 1.7868x; 1.7868x over previous
#include <cuda_runtime.h>
#include <math.h>

#define N_NODES 256
#define E_EDGES 320
#define DE      640
#define HV      128
#define MV      128
#define DISD    8
#define ANGD    16
#define CAP     64
#define WATT_LD 416
#define WLNK_LD 264

// ---------------- scratch ----------------
__device__ int   g_U[DE], g_V[DE];
__device__ float g_norm[DE * 3];
__device__ float g_align[DE];
__device__ float g_a[DE * MV];
__device__ float g_b[DE * MV];
__device__ float g_att[DE * MV];
__device__ float g_attsum[4 * MV];
__device__ float g_wc[ANGD * MV];        // W_att[:,400:416] transposed [k][m]
__device__ float g_sw[N_NODES * CAP];    // per-node normalized softmax weights
__device__ int   g_adjU_cnt[N_NODES], g_adjV_cnt[N_NODES];
__device__ int   g_adjU[N_NODES * CAP], g_adjV[N_NODES * CAP];

__device__ __forceinline__ float dot4(float4 a, float4 b) {
    return a.x * b.x + a.y * b.y + a.z * b.z + a.w * b.w;
}

// ============ K1: self-decoding fused GEMM + adjacency + misc ================
// bid <  160 : GEMM block. cg=bid&1 (64 cols), eg=bid>>1 (4 fwd edges).
// bid in [160,192): adjacency (8 warps = 8 nodes each)
// bid == 192 : wc transpose + attsum zero
__global__ void __launch_bounds__(256) k_main(
        const float* __restrict__ hv, const float* __restrict__ he,
        const float* __restrict__ q,
        const float* __restrict__ vew1, const float* __restrict__ vew2,
        const float* __restrict__ W_dis, const float* __restrict__ b_dis,
        const float* __restrict__ W_att,
        const float* __restrict__ W_align, const float* __restrict__ b_align,
        const float* __restrict__ W_link, const float* __restrict__ b_link,
        float* __restrict__ out) {
    const int bid = blockIdx.x;
    const int t = threadIdx.x;

    if (bid < 160) {
        const int cg = bid & 1;
        const int eg = bid >> 1;
        const int e0 = eg * 4;
        const int ml = t & 63;
        const int h  = t >> 6;                 // 4-way split-K; also edge id in decode
        const int m  = cg * 64 + ml;

        __shared__ int s_u[4], s_v[4];
        __shared__ __align__(16) float su[4][HV], sv[4][HV], sdis[4][DISD];
        __shared__ float spart[3][24][64];

        // --- self-decode: 64 threads scan each edge's one-hot columns ---
        {
            int e = e0 + h;
            #pragma unroll
            for (int j = 0; j < 4; j++) {
                int n = (t & 63) + 64 * j;
                if (vew1[n * E_EDGES + e] != 0.0f) s_u[h] = n;   // unique writer
                if (vew2[n * E_EDGES + e] != 0.0f) s_v[h] = n;
            }
        }
        __syncthreads();

        // --- stage hv tiles, geometry, indices, align ---
        #pragma unroll
        for (int j = 0; j < 4; j++) {
            if (t < 128) su[j][t] = hv[s_u[j] * HV + t];
            else         sv[j][t - 128] = hv[s_v[j] * HV + (t - 128)];
        }
        if (t < 4) {
            int e = e0 + t, u = s_u[t], v = s_v[t];
            float qx = q[v * 3 + 0] - q[u * 3 + 0];
            float qy = q[v * 3 + 1] - q[u * 3 + 1];
            float qz = q[v * 3 + 2] - q[u * 3 + 2];
            float dis = sqrtf(qx * qx + qy * qy + qz * qz) + 1e-6f;
            float inv = 1.0f / dis;
            if (cg == 0) {
                g_norm[e * 3 + 0] = qx * inv;
                g_norm[e * 3 + 1] = qy * inv;
                g_norm[e * 3 + 2] = qz * inv;
                g_norm[(e + E_EDGES) * 3 + 0] = -qx * inv;
                g_norm[(e + E_EDGES) * 3 + 1] = -qy * inv;
                g_norm[(e + E_EDGES) * 3 + 2] = -qz * inv;
            }
            float td = tanhf(dis);
            #pragma unroll
            for (int k = 0; k < DISD; k++)
                sdis[t][k] = tanhf(td * W_dis[k] + b_dis[k]);
        }
        if (cg == 0 && t >= 4 && t < 8) {
            int ei = t - 4, e = e0 + ei;
            g_U[e] = s_u[ei]; g_V[e] = s_v[ei];
            g_U[e + E_EDGES] = s_v[ei]; g_V[e + E_EDGES] = s_u[ei];
        }
        if (cg == 0 && t >= 128) {             // warps 4..7: align for edge w-4
            int w = t >> 5, lane = t & 31;
            int e = e0 + (w - 4);
            float val = 0.0f;
            #pragma unroll
            for (int k = 0; k < 4; k++) {
                int c = lane + 32 * k;
                val += he[e * HV + c] * W_align[c];
            }
            #pragma unroll
            for (int s = 16; s > 0; s >>= 1)
                val += __shfl_down_sync(0xFFFFFFFFu, val, s);
            if (lane == 0) {
                float al = val + b_align[0];
                g_align[e] = al;
                g_align[e + E_EDGES] = al;
            }
        }
        __syncthreads();

        // --- GEMM: 4 edges x {a fwd/rev, b fwd/rev, me fwd/rev} ---
        float acc[4][6];
        #pragma unroll
        for (int ei = 0; ei < 4; ei++)
            #pragma unroll
            for (int c = 0; c < 6; c++) acc[ei][c] = 0.0f;

        const float4* wrow = (const float4*)(W_att + m * WATT_LD);
        const float4* lrow = (const float4*)(W_link + m * WLNK_LD);
        const int k0 = h * 8;
        #pragma unroll
        for (int kk = 0; kk < 8; kk++) {
            int k = k0 + kk;
            float4 wva = wrow[k];              // A: hv_v  cols [0,128)
            float4 wua = wrow[34 + k];         // A: hv_u  cols [136,264)
            float4 wvb = wrow[66 + k];         // b: hv_v  cols [264,392)
            float4 wum = lrow[k];              // link: hv_u
            float4 wvm = lrow[34 + k];         // link: hv_v
            #pragma unroll
            for (int ei = 0; ei < 4; ei++) {
                float4 uu = ((const float4*)su[ei])[k];
                float4 vv = ((const float4*)sv[ei])[k];
                acc[ei][0] += dot4(vv, wva) + dot4(uu, wua);
                acc[ei][1] += dot4(uu, wva) + dot4(vv, wua);  // reverse: swap
                acc[ei][2] += dot4(vv, wvb);
                acc[ei][3] += dot4(uu, wvb);
                acc[ei][4] += dot4(uu, wum) + dot4(vv, wvm);
                acc[ei][5] += dot4(vv, wum) + dot4(uu, wvm);
            }
        }
        if (h == 0) {                          // dis block (shared fwd/rev)
            #pragma unroll
            for (int kk = 0; kk < 2; kk++) {
                float4 wda = wrow[32 + kk];    // A: dis cols [128,136)
                float4 wdb = wrow[98 + kk];    // b: dis cols [392,400)
                float4 wdm = lrow[32 + kk];    // link: dis
                #pragma unroll
                for (int ei = 0; ei < 4; ei++) {
                    float4 dd = ((const float4*)sdis[ei])[kk];
                    float da = dot4(dd, wda), db = dot4(dd, wdb), dm = dot4(dd, wdm);
                    acc[ei][0] += da; acc[ei][1] += da;
                    acc[ei][2] += db; acc[ei][3] += db;
                    acc[ei][4] += dm; acc[ei][5] += dm;
                }
            }
        }

        if (h > 0) {
            #pragma unroll
            for (int ei = 0; ei < 4; ei++)
                #pragma unroll
                for (int c = 0; c < 6; c++)
                    spart[h - 1][ei * 6 + c][ml] = acc[ei][c];
        }
        __syncthreads();
        if (h == 0) {
            #pragma unroll
            for (int p = 0; p < 3; p++)
                #pragma unroll
                for (int ei = 0; ei < 4; ei++)
                    #pragma unroll
                    for (int c = 0; c < 6; c++)
                        acc[ei][c] += spart[p][ei * 6 + c][ml];
            float bl2 = 2.0f * b_link[m];
            #pragma unroll
            for (int ei = 0; ei < 4; ei++) {
                int e = e0 + ei;
                g_a[e * MV + m] = acc[ei][0];
                g_a[(e + E_EDGES) * MV + m] = acc[ei][1];
                g_b[e * MV + m] = acc[ei][2];
                g_b[(e + E_EDGES) * MV + m] = acc[ei][3];
                float x = acc[ei][4] + acc[ei][5] + bl2;
                out[N_NODES * MV + e * MV + m] = (x >= 0.0f) ? x : 0.01f * x;
            }
        }
    } else if (bid < 192) {
        // ---- adjacency: one warp per node, ballot-ordered append ----
        int lane = t & 31;
        int n = (bid - 160) * 8 + (t >> 5);
        unsigned lml = (1u << lane) - 1u;
        int cu = 0, cv = 0;
        for (int e0 = 0; e0 < E_EDGES; e0 += 32) {
            int e = e0 + lane;
            float a = vew1[n * E_EDGES + e];
            float c = vew2[n * E_EDGES + e];
            unsigned m1 = __ballot_sync(0xFFFFFFFFu, a != 0.0f);
            unsigned m2 = __ballot_sync(0xFFFFFFFFu, c != 0.0f);
            if (a != 0.0f) g_adjU[n * CAP + cu + __popc(m1 & lml)] = e;
            if (c != 0.0f) g_adjV[n * CAP + cv + __popc(m2 & lml)] = e;
            cu += __popc(m1); cv += __popc(m2);
        }
        for (int e0 = 0; e0 < E_EDGES; e0 += 32) {
            int e = e0 + lane;
            float a = vew1[n * E_EDGES + e];
            float c = vew2[n * E_EDGES + e];
            unsigned m1 = __ballot_sync(0xFFFFFFFFu, c != 0.0f);
            unsigned m2 = __ballot_sync(0xFFFFFFFFu, a != 0.0f);
            if (c != 0.0f) g_adjU[n * CAP + cu + __popc(m1 & lml)] = e + E_EDGES;
            if (a != 0.0f) g_adjV[n * CAP + cv + __popc(m2 & lml)] = e + E_EDGES;
            cu += __popc(m1); cv += __popc(m2);
        }
        if (lane == 0) { g_adjU_cnt[n] = cu; g_adjV_cnt[n] = cv; }
    } else {
        for (int j = t; j < 4 * MV; j += 256) g_attsum[j] = 0.0f;
        for (int j = t; j < ANGD * MV; j += 256) {
            int k = j >> 7, mm = j & 127;
            g_wc[j] = W_att[mm * WATT_LD + 400 + k];
        }
    }
}

// ============ K2: attend + per-node softmax weights ==========================
__global__ void __launch_bounds__(128) k_attend(const float* __restrict__ W_ang,
                                                const float* __restrict__ b_ang) {
    const int bid = blockIdx.x;
    const int t = threadIdx.x;
    if (bid < DE) {
        int i = bid;
        __shared__ float sh_t[ANGD];
        float wc[ANGD];
        #pragma unroll
        for (int k = 0; k < ANGD; k++) wc[k] = g_wc[k * MV + t];
        float ai = g_a[i * MV + t];
        float nix = g_norm[i * 3 + 0], niy = g_norm[i * 3 + 1], niz = g_norm[i * 3 + 2];
        int u = g_U[i];
        int cnt = g_adjU_cnt[u];
        float amax = 0.0f;                     // relu floor
        for (int idx = 0; idx < cnt; idx++) {
            int j = g_adjU[u * CAP + idx];
            if (t < ANGD) {
                float ang = nix * g_norm[j * 3 + 0] + niy * g_norm[j * 3 + 1]
                          + niz * g_norm[j * 3 + 2];
                sh_t[t] = tanhf(ang * W_ang[t] + b_ang[t]);
            }
            __syncthreads();
            float c = 0.0f;
            #pragma unroll
            for (int k = 0; k < ANGD; k++) c += sh_t[k] * wc[k];
            amax = fmaxf(amax, ai + g_b[j * MV + t] + c);
            __syncthreads();
        }
        g_att[i * MV + t] = amax;
        atomicAdd(&g_attsum[(i & 3) * MV + t], amax);
    } else {
        // node softmax weights: one warp per node
        int lane = t & 31;
        int n = (bid - DE) * 4 + (t >> 5);
        int cnt = g_adjV_cnt[n];
        if (cnt == 0) return;
        if (cnt <= 32) {
            float a = (lane < cnt) ? g_align[g_adjV[n * CAP + lane]] : -1e30f;
            float mx = a;
            #pragma unroll
            for (int s = 16; s > 0; s >>= 1)
                mx = fmaxf(mx, __shfl_xor_sync(0xFFFFFFFFu, mx, s));
            float w = (lane < cnt) ? expf(a - mx) : 0.0f;
            float den = w;
            #pragma unroll
            for (int s = 16; s > 0; s >>= 1)
                den += __shfl_xor_sync(0xFFFFFFFFu, den, s);
            if (lane < cnt) g_sw[n * CAP + lane] = w / den;
        } else if (lane == 0) {                // safety fallback (never hit)
            float mx = -1e30f;
            for (int idx = 0; idx < cnt; idx++)
                mx = fmaxf(mx, g_align[g_adjV[n * CAP + idx]]);
            float den = 0.0f;
            for (int idx = 0; idx < cnt; idx++)
                den += expf(g_align[g_adjV[n * CAP + idx]] - mx);
            for (int idx = 0; idx < cnt; idx++)
                g_sw[n * CAP + idx] = expf(g_align[g_adjV[n * CAP + idx]] - mx) / den;
        }
    }
}

// ============ K3: weighted gather + elu -> mv ================================
__global__ void __launch_bounds__(128) k_mv(float* __restrict__ out) {
    int n = blockIdx.x;
    int t = threadIdx.x;
    int cnt = g_adjV_cnt[n];
    float r;
    if (cnt == 0) {
        r = (g_attsum[t] + g_attsum[MV + t] + g_attsum[2 * MV + t]
             + g_attsum[3 * MV + t]) * (1.0f / (float)DE);
    } else {
        float acc = 0.0f;
        int idx = 0;
        for (; idx + 2 <= cnt; idx += 2) {     // 2-way ILP
            int d0 = g_adjV[n * CAP + idx];
            int d1 = g_adjV[n * CAP + idx + 1];
            float w0 = g_sw[n * CAP + idx];
            float w1 = g_sw[n * CAP + idx + 1];
            acc += w0 * g_att[d0 * MV + t] + w1 * g_att[d1 * MV + t];
        }
        if (idx < cnt)
            acc += g_sw[n * CAP + idx] * g_att[g_adjV[n * CAP + idx] * MV + t];
        r = acc;
    }
    out[n * MV + t] = (r > 0.0f) ? r : expm1f(r);
}

// ---------------- launch ----------------
extern "C" void kernel_launch(void* const* d_in, const int* in_sizes, int n_in,
                              void* d_out, int out_size) {
    const float* hv      = (const float*)d_in[0];
    const float* he      = (const float*)d_in[1];
    const float* q       = (const float*)d_in[3];
    const float* vew1    = (const float*)d_in[4];
    const float* vew2    = (const float*)d_in[5];
    const float* W_dis   = (const float*)d_in[8];
    const float* b_dis   = (const float*)d_in[9];
    const float* W_ang   = (const float*)d_in[10];
    const float* b_ang   = (const float*)d_in[11];
    const float* W_att   = (const float*)d_in[12];
    const float* W_align = (const float*)d_in[13];
    const float* b_align = (const float*)d_in[14];
    const float* W_link  = (const float*)d_in[15];
    const float* b_link  = (const float*)d_in[16];
    float* out = (float*)d_out;

    k_main<<<193, 256>>>(hv, he, q, vew1, vew2, W_dis, b_dis, W_att,
                         W_align, b_align, W_link, b_link, out);
    k_attend<<<DE + 64, 128>>>(W_ang, b_ang);
    k_mv<<<N_NODES, 128>>>(out);
}

// round 6
// speedup vs baseline: 1.8857x; 1.0554x over previous
#include <cuda_runtime.h>
#include <math.h>

#define N_NODES 256
#define E_EDGES 320
#define DE      640
#define HV      128
#define MV      128
#define DISD    8
#define ANGD    16
#define CAP     64
#define WATT_LD 416
#define WLNK_LD 264

// ---------------- scratch ----------------
__device__ int   g_U[DE], g_V[DE];
__device__ float g_norm[DE * 3];
__device__ float g_align[DE];
__device__ float g_a[DE * MV];
__device__ float g_b[DE * MV];
__device__ float g_att[DE * MV];
__device__ float g_attsum[4 * MV];
__device__ float g_wc[ANGD * MV];        // W_att[:,400:416] transposed [k][m]
__device__ float g_sw[N_NODES * CAP];    // per-node normalized softmax weights
__device__ int   g_adjU_cnt[N_NODES], g_adjV_cnt[N_NODES];
__device__ int   g_adjU[N_NODES * CAP], g_adjV[N_NODES * CAP];

__device__ __forceinline__ float dot4(float4 a, float4 b) {
    return a.x * b.x + a.y * b.y + a.z * b.z + a.w * b.w;
}
__device__ __forceinline__ float4 f4add(float4 a, float4 b) {
    return make_float4(a.x + b.x, a.y + b.y, a.z + b.z, a.w + b.w);
}
__device__ __forceinline__ float4 f4sub(float4 a, float4 b) {
    return make_float4(a.x - b.x, a.y - b.y, a.z - b.z, a.w - b.w);
}

// ============ K1: self-decoding fused GEMM + adjacency + misc ================
__global__ void __launch_bounds__(256) k_main(
        const float* __restrict__ hv, const float* __restrict__ he,
        const float* __restrict__ q,
        const float* __restrict__ vew1, const float* __restrict__ vew2,
        const float* __restrict__ W_dis, const float* __restrict__ b_dis,
        const float* __restrict__ W_att,
        const float* __restrict__ W_align, const float* __restrict__ b_align,
        const float* __restrict__ W_link, const float* __restrict__ b_link,
        float* __restrict__ out) {
    const int bid = blockIdx.x;
    const int t = threadIdx.x;

    if (bid < 160) {
        const int cg = bid & 1;
        const int eg = bid >> 1;
        const int e0 = eg * 4;
        const int ml = t & 63;
        const int h  = t >> 6;                 // 4-way split-K
        const int m  = cg * 64 + ml;

        __shared__ int s_u[4], s_v[4];
        __shared__ __align__(16) float sS[4][HV], sD[4][HV], sdis[4][DISD];
        __shared__ float spart[3][20][64];

        // --- decode: one float4 per matrix covers this block's 4 edges ---
        {
            float4 a1 = *(const float4*)(vew1 + t * E_EDGES + e0);
            float4 a2 = *(const float4*)(vew2 + t * E_EDGES + e0);
            if (a1.x != 0.0f) s_u[0] = t;
            if (a1.y != 0.0f) s_u[1] = t;
            if (a1.z != 0.0f) s_u[2] = t;
            if (a1.w != 0.0f) s_u[3] = t;
            if (a2.x != 0.0f) s_v[0] = t;
            if (a2.y != 0.0f) s_v[1] = t;
            if (a2.z != 0.0f) s_v[2] = t;
            if (a2.w != 0.0f) s_v[3] = t;
        }
        __syncthreads();

        // --- stage S/D tiles + geometry + indices + align ---
        {
            int half = t >> 7, c = t & 127;
            #pragma unroll
            for (int j = 0; j < 2; j++) {
                int ei = half * 2 + j;
                float hu = hv[s_u[ei] * HV + c];
                float hw = hv[s_v[ei] * HV + c];
                sS[ei][c] = 0.5f * (hu + hw);
                sD[ei][c] = 0.5f * (hw - hu);
            }
        }
        if (t < 4) {
            int e = e0 + t, u = s_u[t], v = s_v[t];
            float qx = q[v * 3 + 0] - q[u * 3 + 0];
            float qy = q[v * 3 + 1] - q[u * 3 + 1];
            float qz = q[v * 3 + 2] - q[u * 3 + 2];
            float dis = sqrtf(qx * qx + qy * qy + qz * qz) + 1e-6f;
            float inv = 1.0f / dis;
            if (cg == 0) {
                g_norm[e * 3 + 0] = qx * inv;
                g_norm[e * 3 + 1] = qy * inv;
                g_norm[e * 3 + 2] = qz * inv;
                g_norm[(e + E_EDGES) * 3 + 0] = -qx * inv;
                g_norm[(e + E_EDGES) * 3 + 1] = -qy * inv;
                g_norm[(e + E_EDGES) * 3 + 2] = -qz * inv;
            }
            float td = tanhf(dis);
            #pragma unroll
            for (int k = 0; k < DISD; k++)
                sdis[t][k] = tanhf(td * W_dis[k] + b_dis[k]);
        }
        if (cg == 0 && t >= 4 && t < 8) {
            int ei = t - 4, e = e0 + ei;
            g_U[e] = s_u[ei]; g_V[e] = s_v[ei];
            g_U[e + E_EDGES] = s_v[ei]; g_V[e + E_EDGES] = s_u[ei];
        }
        if (cg == 0 && t >= 128) {             // warps 4..7: align logit
            int w = t >> 5, lane = t & 31;
            int e = e0 + (w - 4);
            float val = 0.0f;
            #pragma unroll
            for (int k = 0; k < 4; k++) {
                int c = lane + 32 * k;
                val += he[e * HV + c] * W_align[c];
            }
            #pragma unroll
            for (int s = 16; s > 0; s >>= 1)
                val += __shfl_down_sync(0xFFFFFFFFu, val, s);
            if (lane == 0) {
                float al = val + b_align[0];
                g_align[e] = al;
                g_align[e + E_EDGES] = al;
            }
        }
        __syncthreads();

        // --- GEMM in S/D basis: 5 accumulators per edge ---
        float A1[4], A2[4], B1[4], B2[4], M[4];
        #pragma unroll
        for (int ei = 0; ei < 4; ei++) {
            A1[ei] = 0.f; A2[ei] = 0.f; B1[ei] = 0.f; B2[ei] = 0.f; M[ei] = 0.f;
        }

        const float4* wrow = (const float4*)(W_att + m * WATT_LD);
        const float4* lrow = (const float4*)(W_link + m * WLNK_LD);
        const int k0 = h * 8;
        #pragma unroll
        for (int kk = 0; kk < 8; kk++) {
            int k = k0 + kk;
            float4 wva = wrow[k];              // A: hv_v  cols [0,128)
            float4 wua = wrow[34 + k];         // A: hv_u  cols [136,264)
            float4 wvb = wrow[66 + k];         // b: hv_v  cols [264,392)
            float4 wl  = f4add(lrow[k], lrow[34 + k]);   // link u+v
            float4 ws  = f4add(wva, wua);
            float4 wd  = f4sub(wva, wua);
            #pragma unroll
            for (int ei = 0; ei < 4; ei++) {
                float4 S = ((const float4*)sS[ei])[k];
                float4 D = ((const float4*)sD[ei])[k];
                A1[ei] += dot4(S, ws);
                A2[ei] += dot4(D, wd);
                B1[ei] += dot4(S, wvb);
                B2[ei] += dot4(D, wvb);
                M[ei]  += dot4(S, wl);
            }
        }
        if (h == 0) {                          // dis block: equal fwd/rev
            #pragma unroll
            for (int kk = 0; kk < 2; kk++) {
                float4 wda = wrow[32 + kk];    // A: dis cols [128,136)
                float4 wdb = wrow[98 + kk];    // b: dis cols [392,400)
                float4 wdm = lrow[32 + kk];    // link: dis
                #pragma unroll
                for (int ei = 0; ei < 4; ei++) {
                    float4 dd = ((const float4*)sdis[ei])[kk];
                    A1[ei] += dot4(dd, wda);
                    B1[ei] += dot4(dd, wdb);
                    M[ei]  += dot4(dd, wdm);
                }
            }
        }

        if (h > 0) {
            #pragma unroll
            for (int ei = 0; ei < 4; ei++) {
                spart[h - 1][ei * 5 + 0][ml] = A1[ei];
                spart[h - 1][ei * 5 + 1][ml] = A2[ei];
                spart[h - 1][ei * 5 + 2][ml] = B1[ei];
                spart[h - 1][ei * 5 + 3][ml] = B2[ei];
                spart[h - 1][ei * 5 + 4][ml] = M[ei];
            }
        }
        __syncthreads();
        if (h == 0) {
            #pragma unroll
            for (int p = 0; p < 3; p++)
                #pragma unroll
                for (int ei = 0; ei < 4; ei++) {
                    A1[ei] += spart[p][ei * 5 + 0][ml];
                    A2[ei] += spart[p][ei * 5 + 1][ml];
                    B1[ei] += spart[p][ei * 5 + 2][ml];
                    B2[ei] += spart[p][ei * 5 + 3][ml];
                    M[ei]  += spart[p][ei * 5 + 4][ml];
                }
            float bl = b_link[m];
            #pragma unroll
            for (int ei = 0; ei < 4; ei++) {
                int e = e0 + ei;
                g_a[e * MV + m]             = A1[ei] + A2[ei];
                g_a[(e + E_EDGES) * MV + m] = A1[ei] - A2[ei];
                g_b[e * MV + m]             = B1[ei] + B2[ei];
                g_b[(e + E_EDGES) * MV + m] = B1[ei] - B2[ei];
                float x = 2.0f * (M[ei] + bl);
                out[N_NODES * MV + e * MV + m] = (x >= 0.0f) ? x : 0.01f * x;
            }
        }
    } else if (bid < 192) {
        // ---- adjacency: one warp per node, ballot-ordered append ----
        int lane = t & 31;
        int n = (bid - 160) * 8 + (t >> 5);
        unsigned lml = (1u << lane) - 1u;
        int cu = 0, cv = 0;
        for (int e0 = 0; e0 < E_EDGES; e0 += 32) {
            int e = e0 + lane;
            float a = vew1[n * E_EDGES + e];
            float c = vew2[n * E_EDGES + e];
            unsigned m1 = __ballot_sync(0xFFFFFFFFu, a != 0.0f);
            unsigned m2 = __ballot_sync(0xFFFFFFFFu, c != 0.0f);
            if (a != 0.0f) g_adjU[n * CAP + cu + __popc(m1 & lml)] = e;
            if (c != 0.0f) g_adjV[n * CAP + cv + __popc(m2 & lml)] = e;
            cu += __popc(m1); cv += __popc(m2);
        }
        for (int e0 = 0; e0 < E_EDGES; e0 += 32) {
            int e = e0 + lane;
            float a = vew1[n * E_EDGES + e];
            float c = vew2[n * E_EDGES + e];
            unsigned m1 = __ballot_sync(0xFFFFFFFFu, c != 0.0f);
            unsigned m2 = __ballot_sync(0xFFFFFFFFu, a != 0.0f);
            if (c != 0.0f) g_adjU[n * CAP + cu + __popc(m1 & lml)] = e + E_EDGES;
            if (a != 0.0f) g_adjV[n * CAP + cv + __popc(m2 & lml)] = e + E_EDGES;
            cu += __popc(m1); cv += __popc(m2);
        }
        if (lane == 0) { g_adjU_cnt[n] = cu; g_adjV_cnt[n] = cv; }
    } else {
        for (int j = t; j < 4 * MV; j += 256) g_attsum[j] = 0.0f;
        for (int j = t; j < ANGD * MV; j += 256) {
            int k = j >> 7, mm = j & 127;
            g_wc[j] = W_att[mm * WATT_LD + 400 + k];
        }
    }
}

// ============ K2: sync-free attend (warp tasks) + node softmax weights =======
__global__ void __launch_bounds__(256) k_attend(const float* __restrict__ W_ang,
                                                const float* __restrict__ b_ang) {
    const int t = threadIdx.x;
    const int lane = t & 31;
    const int gw = blockIdx.x * 8 + (t >> 5);

    if (gw < DE * 4) {
        int i = gw >> 2;
        int m = (gw & 3) * 32 + lane;
        float wang = 0.f, bang = 0.f;
        if (lane < ANGD) { wang = W_ang[lane]; bang = b_ang[lane]; }
        float wc[ANGD];
        #pragma unroll
        for (int k = 0; k < ANGD; k++) wc[k] = g_wc[k * MV + m];
        float ai = g_a[i * MV + m];
        float nix = g_norm[i * 3 + 0], niy = g_norm[i * 3 + 1], niz = g_norm[i * 3 + 2];
        int u = g_U[i];
        int cnt = g_adjU_cnt[u];
        float amax = 0.0f;                     // relu floor
        for (int idx = 0; idx < cnt; idx++) {
            int j = g_adjU[u * CAP + idx];
            float ang = nix * g_norm[j * 3 + 0] + niy * g_norm[j * 3 + 1]
                      + niz * g_norm[j * 3 + 2];
            float sh = 0.0f;
            if (lane < ANGD) sh = tanhf(ang * wang + bang);
            float c = 0.0f;
            #pragma unroll
            for (int k = 0; k < ANGD; k++)
                c += __shfl_sync(0xFFFFFFFFu, sh, k) * wc[k];
            amax = fmaxf(amax, ai + g_b[j * MV + m] + c);
        }
        g_att[i * MV + m] = amax;
        atomicAdd(&g_attsum[(i & 3) * MV + m], amax);
    } else if (gw < DE * 4 + N_NODES) {
        // node softmax weights: one warp per node
        int n = gw - DE * 4;
        int cnt = g_adjV_cnt[n];
        if (cnt == 0) return;
        if (cnt <= 32) {
            float a = (lane < cnt) ? g_align[g_adjV[n * CAP + lane]] : -1e30f;
            float mx = a;
            #pragma unroll
            for (int s = 16; s > 0; s >>= 1)
                mx = fmaxf(mx, __shfl_xor_sync(0xFFFFFFFFu, mx, s));
            float w = (lane < cnt) ? expf(a - mx) : 0.0f;
            float den = w;
            #pragma unroll
            for (int s = 16; s > 0; s >>= 1)
                den += __shfl_xor_sync(0xFFFFFFFFu, den, s);
            if (lane < cnt) g_sw[n * CAP + lane] = w / den;
        } else if (lane == 0) {                // safety fallback
            float mx = -1e30f;
            for (int idx = 0; idx < cnt; idx++)
                mx = fmaxf(mx, g_align[g_adjV[n * CAP + idx]]);
            float den = 0.0f;
            for (int idx = 0; idx < cnt; idx++)
                den += expf(g_align[g_adjV[n * CAP + idx]] - mx);
            for (int idx = 0; idx < cnt; idx++)
                g_sw[n * CAP + idx] = expf(g_align[g_adjV[n * CAP + idx]] - mx) / den;
        }
    }
}

// ============ K3: weighted gather + elu -> mv ================================
__global__ void __launch_bounds__(128) k_mv(float* __restrict__ out) {
    int n = blockIdx.x;
    int t = threadIdx.x;
    int cnt = g_adjV_cnt[n];
    float r;
    if (cnt == 0) {
        r = (g_attsum[t] + g_attsum[MV + t] + g_attsum[2 * MV + t]
             + g_attsum[3 * MV + t]) * (1.0f / (float)DE);
    } else {
        float acc = 0.0f;
        int idx = 0;
        for (; idx + 2 <= cnt; idx += 2) {
            int d0 = g_adjV[n * CAP + idx];
            int d1 = g_adjV[n * CAP + idx + 1];
            float w0 = g_sw[n * CAP + idx];
            float w1 = g_sw[n * CAP + idx + 1];
            acc += w0 * g_att[d0 * MV + t] + w1 * g_att[d1 * MV + t];
        }
        if (idx < cnt)
            acc += g_sw[n * CAP + idx] * g_att[g_adjV[n * CAP + idx] * MV + t];
        r = acc;
    }
    out[n * MV + t] = (r > 0.0f) ? r : expm1f(r);
}

// ---------------- launch ----------------
extern "C" void kernel_launch(void* const* d_in, const int* in_sizes, int n_in,
                              void* d_out, int out_size) {
    const float* hv      = (const float*)d_in[0];
    const float* he      = (const float*)d_in[1];
    const float* q       = (const float*)d_in[3];
    const float* vew1    = (const float*)d_in[4];
    const float* vew2    = (const float*)d_in[5];
    const float* W_dis   = (const float*)d_in[8];
    const float* b_dis   = (const float*)d_in[9];
    const float* W_ang   = (const float*)d_in[10];
    const float* b_ang   = (const float*)d_in[11];
    const float* W_att   = (const float*)d_in[12];
    const float* W_align = (const float*)d_in[13];
    const float* b_align = (const float*)d_in[14];
    const float* W_link  = (const float*)d_in[15];
    const float* b_link  = (const float*)d_in[16];
    float* out = (float*)d_out;

    k_main<<<193, 256>>>(hv, he, q, vew1, vew2, W_dis, b_dis, W_att,
                         W_align, b_align, W_link, b_link, out);
    k_attend<<<(DE * 4 + N_NODES + 7) / 8, 256>>>(W_ang, b_ang);
    k_mv<<<N_NODES, 128>>>(out);
}